// round 1
// baseline (speedup 1.0000x reference)
#include <cuda_runtime.h>
#include <math.h>

// Problem constants
#define NB 8          // batch
#define LL 12         // history length
#define NN 1024       // nodes
#define HH 32         // hidden
#define H2 64         // 2*hidden
#define AF 48         // all_feat = H + ND
#define NDIM 16       // node embedding dim

// Scratch (device globals; no runtime allocation allowed)
__device__ float d_h[8192 * H2];          // [B*N, 64]
__device__ float d_scale[H2];
__device__ float d_shift[H2];
__device__ float d_dy[8192 * HH];         // [B*N, 32]
__device__ float d_Q[2 * 8192 * HH];      // [e, B*N, 32]
__device__ float d_K[2 * 8192 * HH];
__device__ float d_g[2ull * NB * NN * NN]; // 64 MB: normalized masked graphs

// ---------------------------------------------------------------------------
// Kernel 1: h = relu(X @ W1 + b1), X[b*N+n, l] = hd[b, l, n, 0]
// block: 256 threads = 4 rows x 64 cols
__global__ void k_h(const float* __restrict__ hd, const float* __restrict__ W1,
                    const float* __restrict__ b1, float* __restrict__ h) {
    __shared__ float sW[LL * H2];
    __shared__ float sb[H2];
    int tid = threadIdx.x;
    for (int i = tid; i < LL * H2; i += 256) sW[i] = W1[i];
    if (tid < H2) sb[tid] = b1[tid];
    __syncthreads();
    int row = blockIdx.x * 4 + (tid >> 6);
    int col = tid & 63;
    int b = row >> 10, n = row & 1023;
    float acc = sb[col];
#pragma unroll
    for (int l = 0; l < LL; l++)
        acc += hd[((size_t)(b * LL + l) << 10) + n] * sW[l * H2 + col];
    h[(size_t)row * H2 + col] = fmaxf(acc, 0.f);
}

// ---------------------------------------------------------------------------
// Kernel 2: per-column batch-norm stats -> folded scale/shift
__global__ void k_stats(const float* __restrict__ h, const float* __restrict__ gamma,
                        const float* __restrict__ beta,
                        float* __restrict__ scale, float* __restrict__ shift) {
    int c = blockIdx.x;
    float s = 0.f, s2 = 0.f;
    for (int r = threadIdx.x; r < 8192; r += 256) {
        float v = h[(size_t)r * H2 + c];
        s += v; s2 += v * v;
    }
    __shared__ float rs[256], rs2[256];
    rs[threadIdx.x] = s; rs2[threadIdx.x] = s2;
    __syncthreads();
    for (int o = 128; o > 0; o >>= 1) {
        if (threadIdx.x < o) { rs[threadIdx.x] += rs[threadIdx.x + o]; rs2[threadIdx.x] += rs2[threadIdx.x + o]; }
        __syncthreads();
    }
    if (threadIdx.x == 0) {
        float mu = rs[0] * (1.f / 8192.f);
        float var = rs2[0] * (1.f / 8192.f) - mu * mu;
        float sc = gamma[c] * rsqrtf(var + 1e-5f);
        scale[c] = sc;
        shift[c] = beta[c] - mu * sc;
    }
}

// ---------------------------------------------------------------------------
// Kernel 3: dy = BN(h) @ W2 + b2.  block: 256 = 8 rows x 32 cols
__global__ void k_dy(const float* __restrict__ h, const float* __restrict__ scale,
                     const float* __restrict__ shift, const float* __restrict__ W2,
                     const float* __restrict__ b2, float* __restrict__ dy) {
    __shared__ float sW[H2 * HH];
    __shared__ float ssc[H2], ssh[H2];
    __shared__ float sh[8][H2];
    int tid = threadIdx.x;
    for (int i = tid; i < H2 * HH; i += 256) sW[i] = W2[i];
    if (tid < H2) { ssc[tid] = scale[tid]; ssh[tid] = shift[tid]; }
    __syncthreads();
    int row0 = blockIdx.x * 8;
    for (int i = tid; i < 8 * H2; i += 256) {
        int r = i >> 6, c = i & 63;
        sh[r][c] = h[(size_t)(row0 + r) * H2 + c] * ssc[c] + ssh[c];
    }
    __syncthreads();
    int r = tid >> 5, c = tid & 31;
    float acc = b2[c];
#pragma unroll
    for (int k = 0; k < H2; k++) acc += sh[r][k] * sW[k * HH + c];
    dy[(size_t)(row0 + r) * HH + c] = acc;
}

// ---------------------------------------------------------------------------
// Kernel 4: Q/K projections from feat=[dy, emb]. 128 threads = 4 rows x 32 cols
__global__ void k_qk(const float* __restrict__ dy, const float* __restrict__ embd,
                     const float* __restrict__ embu, const float* __restrict__ WQ,
                     const float* __restrict__ WK, float* __restrict__ Q,
                     float* __restrict__ K) {
    __shared__ float sWQ[AF * HH], sWK[AF * HH];
    __shared__ float sf[4][AF];
    int tid = threadIdx.x;
    for (int i = tid; i < AF * HH; i += 128) { sWQ[i] = WQ[i]; sWK[i] = WK[i]; }
    int gr = blockIdx.x * 4;        // 0..16383
    int e = gr >> 13;
    int bn0 = gr & 8191;
    const float* emb = e ? embu : embd;
    for (int i = tid; i < 4 * AF; i += 128) {
        int r = i / AF, c = i % AF;
        int bn = bn0 + r;
        int n = bn & 1023;
        sf[r][c] = (c < HH) ? dy[(size_t)bn * HH + c] : emb[n * NDIM + (c - HH)];
    }
    __syncthreads();
    int r = tid >> 5, c = tid & 31;
    float aq = 0.f, ak = 0.f;
#pragma unroll
    for (int k = 0; k < AF; k++) {
        float f = sf[r][k];
        aq += f * sWQ[k * HH + c];
        ak += f * sWK[k * HH + c];
    }
    size_t o = (size_t)(gr + r) * HH + c;
    Q[o] = aq; K[o] = ak;
}

// ---------------------------------------------------------------------------
// Kernel 5: logits -> exp(l-max)*(adj+1e-7), normalize row -> g.
// Also writes order-1 outputs (s = 2e) with zeroed diagonal, duplicated K_T=2.
// 256 threads, 8 rows per block. smem: sQ[256] + sK[256*33] + sE[8*1024]
__global__ void k_attn(const float* __restrict__ Q, const float* __restrict__ K,
                       const float* __restrict__ adj0, const float* __restrict__ adj1,
                       float* __restrict__ g, float* __restrict__ out) {
    extern __shared__ float smem[];
    float* sQ = smem;                 // 256
    float* sK = smem + 256;           // 256*33 = 8448 (padded: bank-conflict-free)
    float* sE = smem + 256 + 8448;    // 8192
    int tid = threadIdx.x;
    int blk = blockIdx.x;             // 0..2047
    int e = blk >> 10;
    int rb = blk & 1023;
    int b = rb >> 7;
    int row0 = (rb & 127) * 8;
    const float* adj = e ? adj1 : adj0;
    size_t qbase = ((size_t)e * 8192 + b * 1024 + row0) * HH;
    size_t kbase = ((size_t)e * 8192 + b * 1024) * HH;
    sQ[tid] = Q[qbase + tid];

    const float lscale = 0.17677669529663687f; // 1/sqrt(32)
    for (int t = 0; t < 4; t++) {
        __syncthreads();
        for (int i = tid; i < 8192; i += 256) {
            int r = i >> 5, c = i & 31;
            sK[r * 33 + c] = K[kbase + (size_t)t * 8192 + i];
        }
        __syncthreads();
#pragma unroll
        for (int r = 0; r < 8; r++) {
            float acc = 0.f;
#pragma unroll
            for (int k = 0; k < HH; k++) acc += sQ[r * 32 + k] * sK[tid * 33 + k];
            sE[r * 1024 + t * 256 + tid] = acc * lscale;
        }
    }
    __syncthreads();

    int w = tid >> 5, lane = tid & 31;
    int n = row0 + w;
    float mx = -1e30f;
#pragma unroll
    for (int i = 0; i < 32; i++) mx = fmaxf(mx, sE[w * 1024 + i * 32 + lane]);
    for (int o = 16; o > 0; o >>= 1) mx = fmaxf(mx, __shfl_xor_sync(0xffffffffu, mx, o));
    float sum = 0.f;
#pragma unroll
    for (int i = 0; i < 32; i++) {
        int m = i * 32 + lane;
        float v = expf(sE[w * 1024 + m] - mx) * (adj[(size_t)n * 1024 + m] + 1e-7f);
        sE[w * 1024 + m] = v;
        sum += v;
    }
    for (int o = 16; o > 0; o >>= 1) sum += __shfl_xor_sync(0xffffffffu, sum, o);
    float inv = 1.f / sum;
    if (!isfinite(inv)) inv = 0.f;

    size_t gbase = ((size_t)e * 8192 + b * 1024 + n) * 1024;
    size_t obase = (size_t)(2 * e) * (8ull * 1024 * 2048) + ((size_t)b * 1024 + n) * 2048;
#pragma unroll
    for (int i = 0; i < 32; i++) {
        int m = i * 32 + lane;
        float v = sE[w * 1024 + m] * inv;
        g[gbase + m] = v;
        float vo = (m == n) ? 0.f : v;
        out[obase + m] = vo;
        out[obase + 1024 + m] = vo;
    }
}

// ---------------------------------------------------------------------------
// Kernel 6: C = A @ A (A = g per (e,b)), write s = 2e+1 outputs (zero diag, x2).
// 128x128x8 tiling, 256 threads, 8x8 register tile.
__global__ void k_gemm(const float* __restrict__ g, float* __restrict__ out) {
    __shared__ float As[8][128];
    __shared__ float Bs[8][128];
    int eb = blockIdx.z;                      // e*8 + b
    const float* A = g + (size_t)eb * 1024 * 1024;
    int tm = blockIdx.y * 128, tn = blockIdx.x * 128;
    int tid = threadIdx.x;
    int tx = tid & 15, ty = tid >> 4;
    float acc[8][8];
#pragma unroll
    for (int i = 0; i < 8; i++)
#pragma unroll
        for (int j = 0; j < 8; j++) acc[i][j] = 0.f;

    int arow = tid >> 1;
    int acol = (tid & 1) * 4;
    int brow = tid >> 5;
    int bcol = (tid & 31) * 4;

    for (int k0 = 0; k0 < 1024; k0 += 8) {
        float4 av = *(const float4*)&A[(size_t)(tm + arow) * 1024 + k0 + acol];
        float4 bv = *(const float4*)&A[(size_t)(k0 + brow) * 1024 + tn + bcol];
        __syncthreads();
        As[acol + 0][arow] = av.x;
        As[acol + 1][arow] = av.y;
        As[acol + 2][arow] = av.z;
        As[acol + 3][arow] = av.w;
        *(float4*)&Bs[brow][bcol] = bv;
        __syncthreads();
#pragma unroll
        for (int k = 0; k < 8; k++) {
            float a[8], bb[8];
            *(float4*)&a[0] = *(const float4*)&As[k][ty * 8];
            *(float4*)&a[4] = *(const float4*)&As[k][ty * 8 + 4];
            *(float4*)&bb[0] = *(const float4*)&Bs[k][tx * 8];
            *(float4*)&bb[4] = *(const float4*)&Bs[k][tx * 8 + 4];
#pragma unroll
            for (int i = 0; i < 8; i++)
#pragma unroll
                for (int j = 0; j < 8; j++) acc[i][j] += a[i] * bb[j];
        }
    }

    int e = eb >> 3, b = eb & 7;
    size_t obase = (size_t)(2 * e + 1) * (8ull * 1024 * 2048) + (size_t)b * 1024 * 2048;
#pragma unroll
    for (int i = 0; i < 8; i++) {
        int n_ = tm + ty * 8 + i;
#pragma unroll
        for (int j4 = 0; j4 < 8; j4 += 4) {
            int m_ = tn + tx * 8 + j4;
            float4 v = make_float4(acc[i][j4], acc[i][j4 + 1], acc[i][j4 + 2], acc[i][j4 + 3]);
            int d = n_ - m_;
            if (d >= 0 && d < 4) ((float*)&v)[d] = 0.f;
            *(float4*)&out[obase + (size_t)n_ * 2048 + m_] = v;
            *(float4*)&out[obase + (size_t)n_ * 2048 + 1024 + m_] = v;
        }
    }
}

// ---------------------------------------------------------------------------
extern "C" void kernel_launch(void* const* d_in, const int* in_sizes, int n_in,
                              void* d_out, int out_size) {
    const float* hd   = (const float*)d_in[0];   // [8,12,1024,1]
    const float* embd = (const float*)d_in[1];   // [1024,16]
    const float* embu = (const float*)d_in[2];
    const float* adj0 = (const float*)d_in[3];   // [1024,1024]
    const float* adj1 = (const float*)d_in[4];
    const float* W1   = (const float*)d_in[5];   // [12,64]
    const float* b1   = (const float*)d_in[6];
    const float* gam  = (const float*)d_in[7];
    const float* bet  = (const float*)d_in[8];
    const float* W2   = (const float*)d_in[9];   // [64,32]
    const float* b2   = (const float*)d_in[10];
    const float* WQ   = (const float*)d_in[11];  // [48,32]
    const float* WK   = (const float*)d_in[12];
    float* out = (float*)d_out;

    float *ph, *psc, *psh, *pdy, *pQ, *pK, *pg;
    cudaGetSymbolAddress((void**)&ph,  d_h);
    cudaGetSymbolAddress((void**)&psc, d_scale);
    cudaGetSymbolAddress((void**)&psh, d_shift);
    cudaGetSymbolAddress((void**)&pdy, d_dy);
    cudaGetSymbolAddress((void**)&pQ,  d_Q);
    cudaGetSymbolAddress((void**)&pK,  d_K);
    cudaGetSymbolAddress((void**)&pg,  d_g);

    k_h<<<2048, 256>>>(hd, W1, b1, ph);
    k_stats<<<64, 256>>>(ph, gam, bet, psc, psh);
    k_dy<<<1024, 256>>>(ph, psc, psh, W2, b2, pdy);
    k_qk<<<4096, 128>>>(pdy, embd, embu, WQ, WK, pQ, pK);

    int attn_smem = (256 + 256 * 33 + 8 * 1024) * (int)sizeof(float);
    cudaFuncSetAttribute(k_attn, cudaFuncAttributeMaxDynamicSharedMemorySize, attn_smem);
    k_attn<<<2048, 256, attn_smem>>>(pQ, pK, adj0, adj1, pg, out);

    dim3 ggrid(8, 8, 16);
    k_gemm<<<ggrid, 256>>>(pg, out);
}

// round 4
// speedup vs baseline: 2.2724x; 2.2724x over previous
#include <cuda_runtime.h>
#include <cuda_bf16.h>
#include <cstdint>
#include <math.h>

// Problem constants
#define NB 8          // batch
#define LL 12         // history length
#define NN 1024       // nodes
#define HH 32         // hidden
#define H2 64         // 2*hidden
#define AF 48         // all_feat = H + ND
#define NDIM 16       // node embedding dim

// Scratch (device globals; no runtime allocation allowed)
__device__ float d_h[8192 * H2];
__device__ float d_scale[H2];
__device__ float d_shift[H2];
__device__ float d_dy[8192 * HH];
__device__ float d_Q[2 * 8192 * HH];
__device__ float d_K[2 * 8192 * HH];
__device__ float d_g[2ull * NB * NN * NN];            // 64 MB fp32 graphs

// Single dynamic-smem symbol (k_attn only)
extern __shared__ char dynsmem[];

// ---------------------------------------------------------------------------
__device__ __forceinline__ uint32_t f2tf(float x) {
    uint32_t r;
    asm("cvt.rna.tf32.f32 %0, %1;" : "=r"(r) : "f"(x));
    return r;
}
__device__ __forceinline__ void mma_tf32(float* c, const uint32_t* a, const uint32_t* b) {
    asm volatile(
        "mma.sync.aligned.m16n8k8.row.col.f32.tf32.tf32.f32 "
        "{%0,%1,%2,%3}, {%4,%5,%6,%7}, {%8,%9}, {%0,%1,%2,%3};"
        : "+f"(c[0]), "+f"(c[1]), "+f"(c[2]), "+f"(c[3])
        : "r"(a[0]), "r"(a[1]), "r"(a[2]), "r"(a[3]), "r"(b[0]), "r"(b[1]));
}

// ---------------------------------------------------------------------------
// Kernel 1: h = relu(X @ W1 + b1)
__global__ void k_h(const float* __restrict__ hd, const float* __restrict__ W1,
                    const float* __restrict__ b1, float* __restrict__ h) {
    __shared__ float sW[LL * H2];
    __shared__ float sb[H2];
    int tid = threadIdx.x;
    for (int i = tid; i < LL * H2; i += 256) sW[i] = W1[i];
    if (tid < H2) sb[tid] = b1[tid];
    __syncthreads();
    int row = blockIdx.x * 4 + (tid >> 6);
    int col = tid & 63;
    int b = row >> 10, n = row & 1023;
    float acc = sb[col];
#pragma unroll
    for (int l = 0; l < LL; l++)
        acc += hd[((size_t)(b * LL + l) << 10) + n] * sW[l * H2 + col];
    h[(size_t)row * H2 + col] = fmaxf(acc, 0.f);
}

// ---------------------------------------------------------------------------
// Kernel 2: BN stats -> folded scale/shift
__global__ void k_stats(const float* __restrict__ h, const float* __restrict__ gamma,
                        const float* __restrict__ beta,
                        float* __restrict__ scale, float* __restrict__ shift) {
    int c = blockIdx.x;
    float s = 0.f, s2 = 0.f;
    for (int r = threadIdx.x; r < 8192; r += 256) {
        float v = h[(size_t)r * H2 + c];
        s += v; s2 += v * v;
    }
    __shared__ float rs[256], rs2[256];
    rs[threadIdx.x] = s; rs2[threadIdx.x] = s2;
    __syncthreads();
    for (int o = 128; o > 0; o >>= 1) {
        if (threadIdx.x < o) { rs[threadIdx.x] += rs[threadIdx.x + o]; rs2[threadIdx.x] += rs2[threadIdx.x + o]; }
        __syncthreads();
    }
    if (threadIdx.x == 0) {
        float mu = rs[0] * (1.f / 8192.f);
        float var = rs2[0] * (1.f / 8192.f) - mu * mu;
        float sc = gamma[c] * rsqrtf(var + 1e-5f);
        scale[c] = sc;
        shift[c] = beta[c] - mu * sc;
    }
}

// ---------------------------------------------------------------------------
// Kernel 3: dy = BN(h) @ W2 + b2
__global__ void k_dy(const float* __restrict__ h, const float* __restrict__ scale,
                     const float* __restrict__ shift, const float* __restrict__ W2,
                     const float* __restrict__ b2, float* __restrict__ dy) {
    __shared__ float sW[H2 * HH];
    __shared__ float ssc[H2], ssh[H2];
    __shared__ float sh[8][H2];
    int tid = threadIdx.x;
    for (int i = tid; i < H2 * HH; i += 256) sW[i] = W2[i];
    if (tid < H2) { ssc[tid] = scale[tid]; ssh[tid] = shift[tid]; }
    __syncthreads();
    int row0 = blockIdx.x * 8;
    for (int i = tid; i < 8 * H2; i += 256) {
        int r = i >> 6, c = i & 63;
        sh[r][c] = h[(size_t)(row0 + r) * H2 + c] * ssc[c] + ssh[c];
    }
    __syncthreads();
    int r = tid >> 5, c = tid & 31;
    float acc = b2[c];
#pragma unroll
    for (int k = 0; k < H2; k++) acc += sh[r][k] * sW[k * HH + c];
    dy[(size_t)(row0 + r) * HH + c] = acc;
}

// ---------------------------------------------------------------------------
// Kernel 4: Q/K projections
__global__ void k_qk(const float* __restrict__ dy, const float* __restrict__ embd,
                     const float* __restrict__ embu, const float* __restrict__ WQ,
                     const float* __restrict__ WK, float* __restrict__ Q,
                     float* __restrict__ K) {
    __shared__ float sWQ[AF * HH], sWK[AF * HH];
    __shared__ float sf[4][AF];
    int tid = threadIdx.x;
    for (int i = tid; i < AF * HH; i += 128) { sWQ[i] = WQ[i]; sWK[i] = WK[i]; }
    int gr = blockIdx.x * 4;
    int e = gr >> 13;
    int bn0 = gr & 8191;
    const float* emb = e ? embu : embd;
    for (int i = tid; i < 4 * AF; i += 128) {
        int r = i / AF, c = i % AF;
        int bn = bn0 + r;
        int n = bn & 1023;
        sf[r][c] = (c < HH) ? dy[(size_t)bn * HH + c] : emb[n * NDIM + (c - HH)];
    }
    __syncthreads();
    int r = tid >> 5, c = tid & 31;
    float aq = 0.f, ak = 0.f;
#pragma unroll
    for (int k = 0; k < AF; k++) {
        float f = sf[r][k];
        aq += f * sWQ[k * HH + c];
        ak += f * sWK[k * HH + c];
    }
    size_t o = (size_t)(gr + r) * HH + c;
    Q[o] = aq; K[o] = ak;
}

// ---------------------------------------------------------------------------
// Kernel 5: attention -> normalized masked g; order-1 outputs (s=2e)
__global__ void k_attn(const float* __restrict__ Q, const float* __restrict__ K,
                       const float* __restrict__ adj0, const float* __restrict__ adj1,
                       float* __restrict__ g, float* __restrict__ out) {
    float* smemf = (float*)dynsmem;
    float* sQ = smemf;
    float* sK = smemf + 256;
    float* sE = smemf + 256 + 8448;
    int tid = threadIdx.x;
    int blk = blockIdx.x;
    int e = blk >> 10;
    int rb = blk & 1023;
    int b = rb >> 7;
    int row0 = (rb & 127) * 8;
    const float* adj = e ? adj1 : adj0;
    size_t qbase = ((size_t)e * 8192 + b * 1024 + row0) * HH;
    size_t kbase = ((size_t)e * 8192 + b * 1024) * HH;
    sQ[tid] = Q[qbase + tid];

    const float lscale = 0.17677669529663687f;
    for (int t = 0; t < 4; t++) {
        __syncthreads();
        for (int i = tid; i < 8192; i += 256) {
            int r = i >> 5, c = i & 31;
            sK[r * 33 + c] = K[kbase + (size_t)t * 8192 + i];
        }
        __syncthreads();
#pragma unroll
        for (int r = 0; r < 8; r++) {
            float acc = 0.f;
#pragma unroll
            for (int k = 0; k < HH; k++) acc += sQ[r * 32 + k] * sK[tid * 33 + k];
            sE[r * 1024 + t * 256 + tid] = acc * lscale;
        }
    }
    __syncthreads();

    int w = tid >> 5, lane = tid & 31;
    int n = row0 + w;
    float mx = -1e30f;
#pragma unroll
    for (int i = 0; i < 32; i++) mx = fmaxf(mx, sE[w * 1024 + i * 32 + lane]);
    for (int o = 16; o > 0; o >>= 1) mx = fmaxf(mx, __shfl_xor_sync(0xffffffffu, mx, o));
    float sum = 0.f;
#pragma unroll
    for (int i = 0; i < 32; i++) {
        int m = i * 32 + lane;
        float v = expf(sE[w * 1024 + m] - mx) * (adj[(size_t)n * 1024 + m] + 1e-7f);
        sE[w * 1024 + m] = v;
        sum += v;
    }
    for (int o = 16; o > 0; o >>= 1) sum += __shfl_xor_sync(0xffffffffu, sum, o);
    float inv = 1.f / sum;
    if (!isfinite(inv)) inv = 0.f;

    size_t gbase = ((size_t)e * 8192 + b * 1024 + n) * 1024;
    size_t obase = (size_t)(2 * e) * (16ull << 20) + ((size_t)b * 1024 + n) * 2048;
#pragma unroll
    for (int i = 0; i < 32; i++) {
        int m = i * 32 + lane;
        float v = sE[w * 1024 + m] * inv;
        g[gbase + m] = v;
        float vo = (m == n) ? 0.f : v;
        out[obase + m] = vo;
        out[obase + 1024 + m] = vo;
    }
}

// ---------------------------------------------------------------------------
// Kernel 6: tf32 mma.sync GEMM: C = g@g per (e,b). 128x128 C tile, 256 thr.
// Warp grid 2(m) x 4(n); warp tile 64x32; m16n8k8 frags 4x4; k-chunk 32.
#define AP 36     // As row pitch (floats): frag reads bank-conflict-free
#define BP 136    // Bs row pitch

__global__ void __launch_bounds__(256, 1)
k_gemm_tf32(const float* __restrict__ g, float* __restrict__ out) {
    __shared__ uint32_t As[128 * AP];   // [i][k]
    __shared__ uint32_t Bs[32 * BP];    // [k][j]
    int tid = threadIdx.x;
    int eb = blockIdx.z;
    int tm = blockIdx.y * 128, tn = blockIdx.x * 128;
    size_t base = (size_t)eb << 20;

    int wid = tid >> 5, lane = tid & 31;
    int gid = lane >> 2, tig = lane & 3;
    int warp_m = wid & 1, warp_n = wid >> 1;
    int rb0 = warp_m * 64;
    int cb0 = warp_n * 32;

    float acc[4][4][4];
#pragma unroll
    for (int i = 0; i < 4; i++)
#pragma unroll
        for (int j = 0; j < 4; j++)
#pragma unroll
            for (int q = 0; q < 4; q++) acc[i][j][q] = 0.f;

    // global load indices
    int ar = tid >> 3, ac4 = (tid & 7) * 4;      // A: 32 rows/pass x 8 float4
    int bk = tid >> 5, bj4 = (tid & 31) * 4;     // B: 8 k-rows/pass x 32 float4

    float4 ra[4], rbv[4];
#pragma unroll
    for (int p = 0; p < 4; p++) {
        ra[p]  = *(const float4*)&g[base + ((size_t)(tm + p * 32 + ar) << 10) + ac4];
        rbv[p] = *(const float4*)&g[base + ((size_t)(p * 8 + bk) << 10) + tn + bj4];
    }

    for (int c = 0; c < 32; c++) {
        __syncthreads();
#pragma unroll
        for (int p = 0; p < 4; p++) {
            uint32_t* a = &As[(p * 32 + ar) * AP + ac4];
            a[0] = f2tf(ra[p].x); a[1] = f2tf(ra[p].y);
            a[2] = f2tf(ra[p].z); a[3] = f2tf(ra[p].w);
            uint32_t* b = &Bs[(p * 8 + bk) * BP + bj4];
            b[0] = f2tf(rbv[p].x); b[1] = f2tf(rbv[p].y);
            b[2] = f2tf(rbv[p].z); b[3] = f2tf(rbv[p].w);
        }
        __syncthreads();
        if (c < 31) {
            int k0 = (c + 1) * 32;
#pragma unroll
            for (int p = 0; p < 4; p++) {
                ra[p]  = *(const float4*)&g[base + ((size_t)(tm + p * 32 + ar) << 10) + k0 + ac4];
                rbv[p] = *(const float4*)&g[base + ((size_t)(k0 + p * 8 + bk) << 10) + tn + bj4];
            }
        }
#pragma unroll
        for (int kk = 0; kk < 32; kk += 8) {
            uint32_t af[4][4], bf[4][2];
#pragma unroll
            for (int mt = 0; mt < 4; mt++) {
                int r = rb0 + mt * 16 + gid;
                af[mt][0] = As[r * AP + kk + tig];
                af[mt][1] = As[(r + 8) * AP + kk + tig];
                af[mt][2] = As[r * AP + kk + tig + 4];
                af[mt][3] = As[(r + 8) * AP + kk + tig + 4];
            }
#pragma unroll
            for (int nt = 0; nt < 4; nt++) {
                int cc = cb0 + nt * 8 + gid;
                bf[nt][0] = Bs[(kk + tig) * BP + cc];
                bf[nt][1] = Bs[(kk + tig + 4) * BP + cc];
            }
#pragma unroll
            for (int mt = 0; mt < 4; mt++)
#pragma unroll
                for (int nt = 0; nt < 4; nt++)
                    mma_tf32(acc[mt][nt], af[mt], bf[nt]);
        }
    }

    // epilogue: zero diagonal, duplicate K_T=2
    int e = eb >> 3, b_ = eb & 7;
    size_t obase = (size_t)(2 * e + 1) * (16ull << 20) + ((size_t)b_ << 10) * 2048;
#pragma unroll
    for (int mt = 0; mt < 4; mt++) {
#pragma unroll
        for (int half = 0; half < 2; half++) {
            int i = tm + rb0 + mt * 16 + gid + half * 8;
            size_t rowb = obase + (size_t)(i - tm + tm) * 2048;
#pragma unroll
            for (int nt = 0; nt < 4; nt++) {
                int j = tn + cb0 + nt * 8 + tig * 2;
                float2 v;
                v.x = acc[mt][nt][half * 2 + 0];
                v.y = acc[mt][nt][half * 2 + 1];
                if (i == j) v.x = 0.f;
                if (i == j + 1) v.y = 0.f;
                *(float2*)&out[rowb + j] = v;
                *(float2*)&out[rowb + 1024 + j] = v;
            }
        }
    }
}

// ---------------------------------------------------------------------------
extern "C" void kernel_launch(void* const* d_in, const int* in_sizes, int n_in,
                              void* d_out, int out_size) {
    const float* hd   = (const float*)d_in[0];
    const float* embd = (const float*)d_in[1];
    const float* embu = (const float*)d_in[2];
    const float* adj0 = (const float*)d_in[3];
    const float* adj1 = (const float*)d_in[4];
    const float* W1   = (const float*)d_in[5];
    const float* b1   = (const float*)d_in[6];
    const float* gam  = (const float*)d_in[7];
    const float* bet  = (const float*)d_in[8];
    const float* W2   = (const float*)d_in[9];
    const float* b2   = (const float*)d_in[10];
    const float* WQ   = (const float*)d_in[11];
    const float* WK   = (const float*)d_in[12];
    float* out = (float*)d_out;

    float *ph, *psc, *psh, *pdy, *pQ, *pK, *pg;
    cudaGetSymbolAddress((void**)&ph,  d_h);
    cudaGetSymbolAddress((void**)&psc, d_scale);
    cudaGetSymbolAddress((void**)&psh, d_shift);
    cudaGetSymbolAddress((void**)&pdy, d_dy);
    cudaGetSymbolAddress((void**)&pQ,  d_Q);
    cudaGetSymbolAddress((void**)&pK,  d_K);
    cudaGetSymbolAddress((void**)&pg,  d_g);

    k_h<<<2048, 256>>>(hd, W1, b1, ph);
    k_stats<<<64, 256>>>(ph, gam, bet, psc, psh);
    k_dy<<<1024, 256>>>(ph, psc, psh, W2, b2, pdy);
    k_qk<<<4096, 128>>>(pdy, embd, embu, WQ, WK, pQ, pK);

    int attn_smem = (256 + 256 * 33 + 8 * 1024) * (int)sizeof(float);
    cudaFuncSetAttribute(k_attn, cudaFuncAttributeMaxDynamicSharedMemorySize, attn_smem);
    k_attn<<<2048, 256, attn_smem>>>(pQ, pK, adj0, adj1, pg, out);

    dim3 ggrid(8, 8, 16);
    k_gemm_tf32<<<ggrid, 256>>>(pg, out);
}

// round 5
// speedup vs baseline: 3.5440x; 1.5596x over previous
#include <cuda_runtime.h>
#include <cuda_fp16.h>
#include <cstdint>
#include <math.h>

// Problem constants
#define NB 8
#define LL 12
#define NN 1024
#define HH 32
#define H2 64
#define AF 48
#define NDIM 16

// Scratch (device globals)
__device__ float d_h[8192 * H2];
__device__ float d_scale[H2];
__device__ float d_shift[H2];
__device__ float d_dy[8192 * HH];
__device__ float d_Q[2 * 8192 * HH];
__device__ float d_K[2 * 8192 * HH];
__device__ __half d_gh[16ull * 1024 * 1024];   // 32 MB fp16 graphs

extern __shared__ char dynsmem[];

// ---------------------------------------------------------------------------
#define SWZ128(o) ((o) ^ (((o) >> 3) & 0x70))
#define CP_ASYNC16(dst, src) asm volatile("cp.async.cg.shared.global [%0], [%1], 16;" :: "r"(dst), "l"(src))
#define CP_COMMIT() asm volatile("cp.async.commit_group;" ::: "memory")
#define CP_WAIT1() asm volatile("cp.async.wait_group 1;" ::: "memory")
#define CP_WAIT0() asm volatile("cp.async.wait_group 0;" ::: "memory")
#define LDSM4(r0, r1, r2, r3, addr) \
    asm volatile("ldmatrix.sync.aligned.m8n8.x4.shared.b16 {%0,%1,%2,%3}, [%4];" \
        : "=r"(r0), "=r"(r1), "=r"(r2), "=r"(r3) : "r"(addr))
#define LDSM4T(r0, r1, r2, r3, addr) \
    asm volatile("ldmatrix.sync.aligned.m8n8.x4.trans.shared.b16 {%0,%1,%2,%3}, [%4];" \
        : "=r"(r0), "=r"(r1), "=r"(r2), "=r"(r3) : "r"(addr))

__device__ __forceinline__ uint32_t smem_u32(const void* p) {
    uint32_t a;
    asm("{ .reg .u64 t; cvta.to.shared.u64 t, %1; cvt.u32.u64 %0, t; }" : "=r"(a) : "l"(p));
    return a;
}
__device__ __forceinline__ void mma_fp16(float* c, const uint32_t* a, const uint32_t* b) {
    asm volatile(
        "mma.sync.aligned.m16n8k16.row.col.f32.f16.f16.f32 "
        "{%0,%1,%2,%3}, {%4,%5,%6,%7}, {%8,%9}, {%0,%1,%2,%3};"
        : "+f"(c[0]), "+f"(c[1]), "+f"(c[2]), "+f"(c[3])
        : "r"(a[0]), "r"(a[1]), "r"(a[2]), "r"(a[3]), "r"(b[0]), "r"(b[1]));
}

// ---------------------------------------------------------------------------
// Kernel 1: h = relu(X @ W1 + b1)
__global__ void k_h(const float* __restrict__ hd, const float* __restrict__ W1,
                    const float* __restrict__ b1, float* __restrict__ h) {
    __shared__ float sW[LL * H2];
    __shared__ float sb[H2];
    int tid = threadIdx.x;
    for (int i = tid; i < LL * H2; i += 256) sW[i] = W1[i];
    if (tid < H2) sb[tid] = b1[tid];
    __syncthreads();
    int row = blockIdx.x * 4 + (tid >> 6);
    int col = tid & 63;
    int b = row >> 10, n = row & 1023;
    float acc = sb[col];
#pragma unroll
    for (int l = 0; l < LL; l++)
        acc += hd[((size_t)(b * LL + l) << 10) + n] * sW[l * H2 + col];
    h[(size_t)row * H2 + col] = fmaxf(acc, 0.f);
}

// ---------------------------------------------------------------------------
// Kernel 2: BN stats -> folded scale/shift
__global__ void k_stats(const float* __restrict__ h, const float* __restrict__ gamma,
                        const float* __restrict__ beta,
                        float* __restrict__ scale, float* __restrict__ shift) {
    int c = blockIdx.x;
    float s = 0.f, s2 = 0.f;
    for (int r = threadIdx.x; r < 8192; r += 256) {
        float v = h[(size_t)r * H2 + c];
        s += v; s2 += v * v;
    }
    __shared__ float rs[256], rs2[256];
    rs[threadIdx.x] = s; rs2[threadIdx.x] = s2;
    __syncthreads();
    for (int o = 128; o > 0; o >>= 1) {
        if (threadIdx.x < o) { rs[threadIdx.x] += rs[threadIdx.x + o]; rs2[threadIdx.x] += rs2[threadIdx.x + o]; }
        __syncthreads();
    }
    if (threadIdx.x == 0) {
        float mu = rs[0] * (1.f / 8192.f);
        float var = rs2[0] * (1.f / 8192.f) - mu * mu;
        float sc = gamma[c] * rsqrtf(var + 1e-5f);
        scale[c] = sc;
        shift[c] = beta[c] - mu * sc;
    }
}

// ---------------------------------------------------------------------------
// Kernel 3: dy = BN(h) @ W2 + b2
__global__ void k_dy(const float* __restrict__ h, const float* __restrict__ scale,
                     const float* __restrict__ shift, const float* __restrict__ W2,
                     const float* __restrict__ b2, float* __restrict__ dy) {
    __shared__ float sW[H2 * HH];
    __shared__ float ssc[H2], ssh[H2];
    __shared__ float sh[8][H2];
    int tid = threadIdx.x;
    for (int i = tid; i < H2 * HH; i += 256) sW[i] = W2[i];
    if (tid < H2) { ssc[tid] = scale[tid]; ssh[tid] = shift[tid]; }
    __syncthreads();
    int row0 = blockIdx.x * 8;
    for (int i = tid; i < 8 * H2; i += 256) {
        int r = i >> 6, c = i & 63;
        sh[r][c] = h[(size_t)(row0 + r) * H2 + c] * ssc[c] + ssh[c];
    }
    __syncthreads();
    int r = tid >> 5, c = tid & 31;
    float acc = b2[c];
#pragma unroll
    for (int k = 0; k < H2; k++) acc += sh[r][k] * sW[k * HH + c];
    dy[(size_t)(row0 + r) * HH + c] = acc;
}

// ---------------------------------------------------------------------------
// Kernel 4: Q/K projections — 32 rows per 256-thread block
__global__ void k_qk(const float* __restrict__ dy, const float* __restrict__ embd,
                     const float* __restrict__ embu, const float* __restrict__ WQ,
                     const float* __restrict__ WK, float* __restrict__ Q,
                     float* __restrict__ K) {
    __shared__ float sWQ[AF * HH], sWK[AF * HH];
    __shared__ float sf[32][AF];
    int tid = threadIdx.x;
    for (int i = tid; i < AF * HH; i += 256) { sWQ[i] = WQ[i]; sWK[i] = WK[i]; }
    int gr0 = blockIdx.x * 32;          // 0..16352
    int e = gr0 >> 13;
    int bn0 = gr0 & 8191;
    const float* emb = e ? embu : embd;
    for (int i = tid; i < 32 * AF; i += 256) {
        int r = i / AF, c = i % AF;
        int bn = bn0 + r;
        int n = bn & 1023;
        sf[r][c] = (c < HH) ? dy[(size_t)bn * HH + c] : emb[n * NDIM + (c - HH)];
    }
    __syncthreads();
    int rr = tid >> 5, c = tid & 31;
#pragma unroll
    for (int p = 0; p < 4; p++) {
        int r = p * 8 + rr;
        float aq = 0.f, ak = 0.f;
#pragma unroll
        for (int k = 0; k < AF; k++) {
            float f = sf[r][k];
            aq += f * sWQ[k * HH + c];
            ak += f * sWK[k * HH + c];
        }
        size_t o = (size_t)(gr0 + r) * HH + c;
        Q[o] = aq; K[o] = ak;
    }
}

// ---------------------------------------------------------------------------
// Kernel 5: attention -> normalized masked g (fp16); order-1 outputs (s=2e)
__global__ void k_attn(const float* __restrict__ Q, const float* __restrict__ K,
                       const float* __restrict__ adj0, const float* __restrict__ adj1,
                       __half* __restrict__ gh, float* __restrict__ out) {
    float* smemf = (float*)dynsmem;
    float* sQ = smemf;
    float* sK = smemf + 256;
    float* sE = smemf + 256 + 8448;
    int tid = threadIdx.x;
    int blk = blockIdx.x;
    int e = blk >> 10;
    int rb = blk & 1023;
    int b = rb >> 7;
    int row0 = (rb & 127) * 8;
    const float* adj = e ? adj1 : adj0;
    size_t qbase = ((size_t)e * 8192 + b * 1024 + row0) * HH;
    size_t kbase = ((size_t)e * 8192 + b * 1024) * HH;
    sQ[tid] = Q[qbase + tid];

    const float lscale = 0.17677669529663687f;
    for (int t = 0; t < 4; t++) {
        __syncthreads();
        for (int i = tid; i < 8192; i += 256) {
            int r = i >> 5, c = i & 31;
            sK[r * 33 + c] = K[kbase + (size_t)t * 8192 + i];
        }
        __syncthreads();
#pragma unroll
        for (int r = 0; r < 8; r++) {
            float acc = 0.f;
#pragma unroll
            for (int k = 0; k < HH; k++) acc += sQ[r * 32 + k] * sK[tid * 33 + k];
            sE[r * 1024 + t * 256 + tid] = acc * lscale;
        }
    }
    __syncthreads();

    int w = tid >> 5, lane = tid & 31;
    int n = row0 + w;
    float mx = -1e30f;
#pragma unroll
    for (int i = 0; i < 32; i++) mx = fmaxf(mx, sE[w * 1024 + i * 32 + lane]);
    for (int o = 16; o > 0; o >>= 1) mx = fmaxf(mx, __shfl_xor_sync(0xffffffffu, mx, o));
    float sum = 0.f;
#pragma unroll
    for (int i = 0; i < 32; i++) {
        int m = i * 32 + lane;
        float v = expf(sE[w * 1024 + m] - mx) * (adj[(size_t)n * 1024 + m] + 1e-7f);
        sE[w * 1024 + m] = v;
        sum += v;
    }
    for (int o = 16; o > 0; o >>= 1) sum += __shfl_xor_sync(0xffffffffu, sum, o);
    float inv = 1.f / sum;
    if (!isfinite(inv)) inv = 0.f;

    size_t gbase = ((size_t)e * 8192 + b * 1024 + n) * 1024;
    size_t obase = (size_t)(2 * e) * (16ull << 20) + ((size_t)b * 1024 + n) * 2048;
#pragma unroll
    for (int i = 0; i < 32; i++) {
        int m = i * 32 + lane;
        float v = sE[w * 1024 + m] * inv;
        gh[gbase + m] = __float2half_rn(v);
        float vo = (m == n) ? 0.f : v;
        out[obase + m] = vo;
        out[obase + 1024 + m] = vo;
    }
}

// ---------------------------------------------------------------------------
// Kernel 6: fp16 mma.sync GEMM with ldmatrix + cp.async double buffering.
// C = g@g per (e,b). 128x128 C tile, 256 thr, warp tile 64x32, k-chunk 64.
#define A_BYTES 16384              // 128 rows x 128B
#define B_PITCH 272                // bytes per k-row (conflict-free ldmatrix.trans)
#define B_BYTES (64 * B_PITCH)     // 17408
#define GEMM_SMEM (2 * A_BYTES + 2 * B_BYTES)   // 67584

__global__ void __launch_bounds__(256, 2)
k_gemm_fp16(const __half* __restrict__ gh, float* __restrict__ out) {
    char* smem = dynsmem;
    uint32_t sb = smem_u32(smem);
    const uint32_t AOFF[2] = {0u, A_BYTES};
    const uint32_t BOFF[2] = {2 * A_BYTES, 2 * A_BYTES + B_BYTES};
    int tid = threadIdx.x;
    int eb = blockIdx.z;
    int tm = blockIdx.y * 128, tn = blockIdx.x * 128;
    size_t base = (size_t)eb << 20;

    int wid = tid >> 5, lane = tid & 31;
    int gid = lane >> 2, tig = lane & 3;
    int warp_m = wid & 1, warp_n = wid >> 1;
    int rb0 = warp_m * 64, cb0 = warp_n * 32;

    float acc[4][4][4];
#pragma unroll
    for (int i = 0; i < 4; i++)
#pragma unroll
        for (int j = 0; j < 4; j++)
#pragma unroll
            for (int q = 0; q < 4; q++) acc[i][j][q] = 0.f;

    // ldmatrix lane address components
    int lr = lane & 7;
    int lm = (lane >> 3) & 1;
    int lk = lane >> 4;

    // cp.async: load one 64-wide k-chunk into buffer `buf`
    auto load_chunk = [&](int c, int buf) {
        int k0 = c * 64;
#pragma unroll
        for (int q = 0; q < 4; q++) {
            int idx = tid + q * 256;
            int r = idx >> 3, s = idx & 7;
            uint32_t dst = sb + AOFF[buf] + SWZ128((uint32_t)(r * 128 + s * 16));
            const __half* src = gh + base + ((size_t)(tm + r) << 10) + k0 + s * 8;
            CP_ASYNC16(dst, src);
        }
#pragma unroll
        for (int q = 0; q < 4; q++) {
            int idx = tid + q * 256;
            int r = idx >> 4, s = idx & 15;
            uint32_t dst = sb + BOFF[buf] + (uint32_t)(r * B_PITCH + s * 16);
            const __half* src = gh + base + ((size_t)(k0 + r) << 10) + tn + s * 8;
            CP_ASYNC16(dst, src);
        }
        CP_COMMIT();
    };

    load_chunk(0, 0);
    for (int c = 0; c < 16; c++) {
        int buf = c & 1;
        if (c < 15) { load_chunk(c + 1, buf ^ 1); CP_WAIT1(); }
        else        { CP_WAIT0(); }
        __syncthreads();
        uint32_t abase = sb + AOFF[buf];
        uint32_t bbase = sb + BOFF[buf];
#pragma unroll
        for (int kk = 0; kk < 64; kk += 16) {
            uint32_t af[4][4], bf[2][4];
#pragma unroll
            for (int mt = 0; mt < 4; mt++) {
                int m = rb0 + mt * 16 + lm * 8 + lr;
                uint32_t addr = abase + SWZ128((uint32_t)(m * 128 + kk * 2 + lk * 16));
                LDSM4(af[mt][0], af[mt][1], af[mt][2], af[mt][3], addr);
            }
#pragma unroll
            for (int nt2 = 0; nt2 < 2; nt2++) {
                int krow = kk + lm * 8 + lr;
                int n = cb0 + nt2 * 16 + lk * 8;
                uint32_t addr = bbase + (uint32_t)(krow * B_PITCH + n * 2);
                LDSM4T(bf[nt2][0], bf[nt2][1], bf[nt2][2], bf[nt2][3], addr);
            }
#pragma unroll
            for (int mt = 0; mt < 4; mt++)
#pragma unroll
                for (int nt = 0; nt < 4; nt++)
                    mma_fp16(acc[mt][nt], af[mt], &bf[nt >> 1][(nt & 1) * 2]);
        }
        __syncthreads();
    }

    // epilogue: zero diagonal, duplicate K_T=2
    int e = eb >> 3, b_ = eb & 7;
    size_t obase = (size_t)(2 * e + 1) * (16ull << 20) + ((size_t)b_ << 10) * 2048;
#pragma unroll
    for (int mt = 0; mt < 4; mt++) {
#pragma unroll
        for (int half = 0; half < 2; half++) {
            int i = tm + rb0 + mt * 16 + gid + half * 8;
            size_t rowb = obase + (size_t)i * 2048;
#pragma unroll
            for (int nt = 0; nt < 4; nt++) {
                int j = tn + cb0 + nt * 8 + tig * 2;
                float2 v;
                v.x = acc[mt][nt][half * 2 + 0];
                v.y = acc[mt][nt][half * 2 + 1];
                if (i == j) v.x = 0.f;
                if (i == j + 1) v.y = 0.f;
                *(float2*)&out[rowb + j] = v;
                *(float2*)&out[rowb + 1024 + j] = v;
            }
        }
    }
}

// ---------------------------------------------------------------------------
extern "C" void kernel_launch(void* const* d_in, const int* in_sizes, int n_in,
                              void* d_out, int out_size) {
    const float* hd   = (const float*)d_in[0];
    const float* embd = (const float*)d_in[1];
    const float* embu = (const float*)d_in[2];
    const float* adj0 = (const float*)d_in[3];
    const float* adj1 = (const float*)d_in[4];
    const float* W1   = (const float*)d_in[5];
    const float* b1   = (const float*)d_in[6];
    const float* gam  = (const float*)d_in[7];
    const float* bet  = (const float*)d_in[8];
    const float* W2   = (const float*)d_in[9];
    const float* b2   = (const float*)d_in[10];
    const float* WQ   = (const float*)d_in[11];
    const float* WK   = (const float*)d_in[12];
    float* out = (float*)d_out;

    float *ph, *psc, *psh, *pdy, *pQ, *pK;
    __half* pgh;
    cudaGetSymbolAddress((void**)&ph,  d_h);
    cudaGetSymbolAddress((void**)&psc, d_scale);
    cudaGetSymbolAddress((void**)&psh, d_shift);
    cudaGetSymbolAddress((void**)&pdy, d_dy);
    cudaGetSymbolAddress((void**)&pQ,  d_Q);
    cudaGetSymbolAddress((void**)&pK,  d_K);
    cudaGetSymbolAddress((void**)&pgh, d_gh);

    k_h<<<2048, 256>>>(hd, W1, b1, ph);
    k_stats<<<64, 256>>>(ph, gam, bet, psc, psh);
    k_dy<<<1024, 256>>>(ph, psc, psh, W2, b2, pdy);
    k_qk<<<512, 256>>>(pdy, embd, embu, WQ, WK, pQ, pK);

    int attn_smem = (256 + 256 * 33 + 8 * 1024) * (int)sizeof(float);
    cudaFuncSetAttribute(k_attn, cudaFuncAttributeMaxDynamicSharedMemorySize, attn_smem);
    k_attn<<<2048, 256, attn_smem>>>(pQ, pK, adj0, adj1, pgh, out);

    cudaFuncSetAttribute(k_gemm_fp16, cudaFuncAttributeMaxDynamicSharedMemorySize, GEMM_SMEM);
    dim3 ggrid(8, 8, 16);
    k_gemm_fp16<<<ggrid, 256, GEMM_SMEM>>>(pgh, out);
}

// round 6
// speedup vs baseline: 3.7285x; 1.0521x over previous
#include <cuda_runtime.h>
#include <cuda_fp16.h>
#include <cstdint>
#include <math.h>

// Problem constants
#define NB 8
#define LL 12
#define NN 1024
#define HH 32
#define H2 64
#define AF 48
#define NDIM 16

// Scratch (device globals)
__device__ float d_h[8192 * H2];
__device__ float d_scale[H2];
__device__ float d_shift[H2];
__device__ float d_dy[8192 * HH];
__device__ float d_Q[2 * 8192 * HH];
__device__ float d_K[2 * 8192 * HH];
__device__ __half d_gh[16ull * 1024 * 1024];   // 32 MB fp16 graphs

extern __shared__ char dynsmem[];

// ---------------------------------------------------------------------------
#define SWZ128(o) ((o) ^ (((o) >> 3) & 0x70))
#define CP_ASYNC16(dst, src) asm volatile("cp.async.cg.shared.global [%0], [%1], 16;" :: "r"(dst), "l"(src))
#define CP_COMMIT() asm volatile("cp.async.commit_group;" ::: "memory")
#define CP_WAIT1() asm volatile("cp.async.wait_group 1;" ::: "memory")
#define CP_WAIT0() asm volatile("cp.async.wait_group 0;" ::: "memory")
#define LDSM4(r0, r1, r2, r3, addr) \
    asm volatile("ldmatrix.sync.aligned.m8n8.x4.shared.b16 {%0,%1,%2,%3}, [%4];" \
        : "=r"(r0), "=r"(r1), "=r"(r2), "=r"(r3) : "r"(addr))
#define LDSM4T(r0, r1, r2, r3, addr) \
    asm volatile("ldmatrix.sync.aligned.m8n8.x4.trans.shared.b16 {%0,%1,%2,%3}, [%4];" \
        : "=r"(r0), "=r"(r1), "=r"(r2), "=r"(r3) : "r"(addr))

__device__ __forceinline__ uint32_t smem_u32(const void* p) {
    uint32_t a;
    asm("{ .reg .u64 t; cvta.to.shared.u64 t, %1; cvt.u32.u64 %0, t; }" : "=r"(a) : "l"(p));
    return a;
}
__device__ __forceinline__ void mma_fp16(float* c, const uint32_t* a, const uint32_t* b) {
    asm volatile(
        "mma.sync.aligned.m16n8k16.row.col.f32.f16.f16.f32 "
        "{%0,%1,%2,%3}, {%4,%5,%6,%7}, {%8,%9}, {%0,%1,%2,%3};"
        : "+f"(c[0]), "+f"(c[1]), "+f"(c[2]), "+f"(c[3])
        : "r"(a[0]), "r"(a[1]), "r"(a[2]), "r"(a[3]), "r"(b[0]), "r"(b[1]));
}

// ---------------------------------------------------------------------------
// Kernel 1: h = relu(X @ W1 + b1)
__global__ void k_h(const float* __restrict__ hd, const float* __restrict__ W1,
                    const float* __restrict__ b1, float* __restrict__ h) {
    __shared__ float sW[LL * H2];
    __shared__ float sb[H2];
    int tid = threadIdx.x;
    for (int i = tid; i < LL * H2; i += 256) sW[i] = W1[i];
    if (tid < H2) sb[tid] = b1[tid];
    __syncthreads();
    int row = blockIdx.x * 4 + (tid >> 6);
    int col = tid & 63;
    int b = row >> 10, n = row & 1023;
    float acc = sb[col];
#pragma unroll
    for (int l = 0; l < LL; l++)
        acc += hd[((size_t)(b * LL + l) << 10) + n] * sW[l * H2 + col];
    h[(size_t)row * H2 + col] = fmaxf(acc, 0.f);
}

// ---------------------------------------------------------------------------
// Kernel 2: BN stats -> folded scale/shift
__global__ void k_stats(const float* __restrict__ h, const float* __restrict__ gamma,
                        const float* __restrict__ beta,
                        float* __restrict__ scale, float* __restrict__ shift) {
    int c = blockIdx.x;
    float s = 0.f, s2 = 0.f;
    for (int r = threadIdx.x; r < 8192; r += 256) {
        float v = h[(size_t)r * H2 + c];
        s += v; s2 += v * v;
    }
    __shared__ float rs[256], rs2[256];
    rs[threadIdx.x] = s; rs2[threadIdx.x] = s2;
    __syncthreads();
    for (int o = 128; o > 0; o >>= 1) {
        if (threadIdx.x < o) { rs[threadIdx.x] += rs[threadIdx.x + o]; rs2[threadIdx.x] += rs2[threadIdx.x + o]; }
        __syncthreads();
    }
    if (threadIdx.x == 0) {
        float mu = rs[0] * (1.f / 8192.f);
        float var = rs2[0] * (1.f / 8192.f) - mu * mu;
        float sc = gamma[c] * rsqrtf(var + 1e-5f);
        scale[c] = sc;
        shift[c] = beta[c] - mu * sc;
    }
}

// ---------------------------------------------------------------------------
// Kernel 3: dy = BN(h) @ W2 + b2
__global__ void k_dy(const float* __restrict__ h, const float* __restrict__ scale,
                     const float* __restrict__ shift, const float* __restrict__ W2,
                     const float* __restrict__ b2, float* __restrict__ dy) {
    __shared__ float sW[H2 * HH];
    __shared__ float ssc[H2], ssh[H2];
    __shared__ float sh[8][H2];
    int tid = threadIdx.x;
    for (int i = tid; i < H2 * HH; i += 256) sW[i] = W2[i];
    if (tid < H2) { ssc[tid] = scale[tid]; ssh[tid] = shift[tid]; }
    __syncthreads();
    int row0 = blockIdx.x * 8;
    for (int i = tid; i < 8 * H2; i += 256) {
        int r = i >> 6, c = i & 63;
        sh[r][c] = h[(size_t)(row0 + r) * H2 + c] * ssc[c] + ssh[c];
    }
    __syncthreads();
    int r = tid >> 5, c = tid & 31;
    float acc = b2[c];
#pragma unroll
    for (int k = 0; k < H2; k++) acc += sh[r][k] * sW[k * HH + c];
    dy[(size_t)(row0 + r) * HH + c] = acc;
}

// ---------------------------------------------------------------------------
// Kernel 4: Q/K projections — 16 rows per 128-thread block (1024 blocks)
__global__ void k_qk(const float* __restrict__ dy, const float* __restrict__ embd,
                     const float* __restrict__ embu, const float* __restrict__ WQ,
                     const float* __restrict__ WK, float* __restrict__ Q,
                     float* __restrict__ K) {
    __shared__ float sWQ[AF * HH], sWK[AF * HH];
    __shared__ float sf[16][AF];
    int tid = threadIdx.x;
    for (int i = tid; i < AF * HH; i += 128) { sWQ[i] = WQ[i]; sWK[i] = WK[i]; }
    int gr0 = blockIdx.x * 16;
    int e = gr0 >> 13;
    int bn0 = gr0 & 8191;
    const float* emb = e ? embu : embd;
    for (int i = tid; i < 16 * AF; i += 128) {
        int r = i / AF, c = i % AF;
        int bn = bn0 + r;
        int n = bn & 1023;
        sf[r][c] = (c < HH) ? dy[(size_t)bn * HH + c] : emb[n * NDIM + (c - HH)];
    }
    __syncthreads();
    int rr = tid >> 5, c = tid & 31;
#pragma unroll
    for (int p = 0; p < 4; p++) {
        int r = p * 4 + rr;
        float aq = 0.f, ak = 0.f;
#pragma unroll
        for (int k = 0; k < AF; k++) {
            float f = sf[r][k];
            aq += f * sWQ[k * HH + c];
            ak += f * sWK[k * HH + c];
        }
        size_t o = (size_t)(gr0 + r) * HH + c;
        Q[o] = aq; K[o] = ak;
    }
}

// ---------------------------------------------------------------------------
// Kernel 5: attention -> normalized masked g (fp16); order-1 outputs (s=2e)
// K tile stored k-major (pitch 265) so each thread register-caches its column.
#define KT_P 265
__global__ void k_attn(const float* __restrict__ Q, const float* __restrict__ K,
                       const float* __restrict__ adj0, const float* __restrict__ adj1,
                       __half* __restrict__ gh, float* __restrict__ out) {
    float* smemf = (float*)dynsmem;
    float* sQ = smemf;                     // 256
    float* sKT = smemf + 256;              // 32 * 265 = 8480
    float* sE = smemf + 256 + 8480;        // 8192
    int tid = threadIdx.x;
    int blk = blockIdx.x;
    int e = blk >> 10;
    int rb = blk & 1023;
    int b = rb >> 7;
    int row0 = (rb & 127) * 8;
    const float* adj = e ? adj1 : adj0;
    size_t qbase = ((size_t)e * 8192 + b * 1024 + row0) * HH;
    size_t kbase = ((size_t)e * 8192 + b * 1024) * HH;
    sQ[tid] = Q[qbase + tid];

    const float lscale = 0.17677669529663687f;
    for (int t = 0; t < 4; t++) {
        __syncthreads();
        for (int i = tid; i < 8192; i += 256) {
            int r = i >> 5, c = i & 31;        // r: col-in-chunk, c: k
            sKT[c * KT_P + r] = K[kbase + (size_t)t * 8192 + i];
        }
        __syncthreads();
        float kreg[32];
#pragma unroll
        for (int k = 0; k < 32; k++) kreg[k] = sKT[k * KT_P + tid];
#pragma unroll
        for (int r = 0; r < 8; r++) {
            float acc = 0.f;
#pragma unroll
            for (int q4 = 0; q4 < 8; q4++) {
                float4 qv = *(const float4*)&sQ[r * 32 + q4 * 4];
                acc += qv.x * kreg[q4 * 4 + 0];
                acc += qv.y * kreg[q4 * 4 + 1];
                acc += qv.z * kreg[q4 * 4 + 2];
                acc += qv.w * kreg[q4 * 4 + 3];
            }
            sE[r * 1024 + t * 256 + tid] = acc * lscale;
        }
    }
    __syncthreads();

    int w = tid >> 5, lane = tid & 31;
    int n = row0 + w;
    float mx = -1e30f;
#pragma unroll
    for (int i = 0; i < 32; i++) mx = fmaxf(mx, sE[w * 1024 + i * 32 + lane]);
    for (int o = 16; o > 0; o >>= 1) mx = fmaxf(mx, __shfl_xor_sync(0xffffffffu, mx, o));
    float sum = 0.f;
#pragma unroll
    for (int i = 0; i < 32; i++) {
        int m = i * 32 + lane;
        float v = expf(sE[w * 1024 + m] - mx) * (adj[(size_t)n * 1024 + m] + 1e-7f);
        sE[w * 1024 + m] = v;
        sum += v;
    }
    for (int o = 16; o > 0; o >>= 1) sum += __shfl_xor_sync(0xffffffffu, sum, o);
    float inv = 1.f / sum;
    if (!isfinite(inv)) inv = 0.f;

    size_t gbase = ((size_t)e * 8192 + b * 1024 + n) * 1024;
    size_t obase = (size_t)(2 * e) * (16ull << 20) + ((size_t)b * 1024 + n) * 2048;
#pragma unroll
    for (int i = 0; i < 32; i++) {
        int m = i * 32 + lane;
        float v = sE[w * 1024 + m] * inv;
        gh[gbase + m] = __float2half_rn(v);
        float vo = (m == n) ? 0.f : v;
        out[obase + m] = vo;
        out[obase + 1024 + m] = vo;
    }
}

// ---------------------------------------------------------------------------
// Kernel 6: fp16 mma.sync GEMM. Block tile 128x256, warp tile 64x64, k-chunk 64,
// cp.async double buffering. 256 threads, 1 CTA/SM.
#define A_BYTES 16384              // 128 rows x 128B
#define B_PITCH 528                // bytes per k-row (512 data + 16 pad)
#define B_BYTES (64 * B_PITCH)     // 33792
#define GEMM_SMEM (2 * A_BYTES + 2 * B_BYTES)   // 100352

__global__ void __launch_bounds__(256, 1)
k_gemm_fp16(const __half* __restrict__ gh, float* __restrict__ out) {
    char* smem = dynsmem;
    uint32_t sb = smem_u32(smem);
    const uint32_t AOFF[2] = {0u, A_BYTES};
    const uint32_t BOFF[2] = {2 * A_BYTES, 2 * A_BYTES + B_BYTES};
    int tid = threadIdx.x;
    int eb = blockIdx.z;
    int tm = blockIdx.y * 128, tn = blockIdx.x * 256;
    size_t base = (size_t)eb << 20;

    int wid = tid >> 5, lane = tid & 31;
    int gid = lane >> 2, tig = lane & 3;
    int warp_m = wid & 1, warp_n = wid >> 1;
    int rb0 = warp_m * 64, cb0 = warp_n * 64;

    float acc[4][8][4];
#pragma unroll
    for (int i = 0; i < 4; i++)
#pragma unroll
        for (int j = 0; j < 8; j++)
#pragma unroll
            for (int q = 0; q < 4; q++) acc[i][j][q] = 0.f;

    int lr = lane & 7;
    int lm = (lane >> 3) & 1;
    int lk = lane >> 4;

    auto load_chunk = [&](int c, int buf) {
        int k0 = c * 64;
#pragma unroll
        for (int q = 0; q < 4; q++) {
            int idx = tid + q * 256;
            int r = idx >> 3, s = idx & 7;
            uint32_t dst = sb + AOFF[buf] + SWZ128((uint32_t)(r * 128 + s * 16));
            const __half* src = gh + base + ((size_t)(tm + r) << 10) + k0 + s * 8;
            CP_ASYNC16(dst, src);
        }
#pragma unroll
        for (int q = 0; q < 8; q++) {
            int idx = tid + q * 256;
            int r = idx >> 5, s = idx & 31;
            uint32_t dst = sb + BOFF[buf] + (uint32_t)(r * B_PITCH + s * 16);
            const __half* src = gh + base + ((size_t)(k0 + r) << 10) + tn + s * 8;
            CP_ASYNC16(dst, src);
        }
        CP_COMMIT();
    };

    load_chunk(0, 0);
    for (int c = 0; c < 16; c++) {
        int buf = c & 1;
        if (c < 15) { load_chunk(c + 1, buf ^ 1); CP_WAIT1(); }
        else        { CP_WAIT0(); }
        __syncthreads();
        uint32_t abase = sb + AOFF[buf];
        uint32_t bbase = sb + BOFF[buf];
#pragma unroll
        for (int kk = 0; kk < 64; kk += 16) {
            uint32_t af[4][4], bf[4][4];
#pragma unroll
            for (int mt = 0; mt < 4; mt++) {
                int m = rb0 + mt * 16 + lm * 8 + lr;
                uint32_t addr = abase + SWZ128((uint32_t)(m * 128 + kk * 2 + lk * 16));
                LDSM4(af[mt][0], af[mt][1], af[mt][2], af[mt][3], addr);
            }
#pragma unroll
            for (int nt2 = 0; nt2 < 4; nt2++) {
                int krow = kk + lm * 8 + lr;
                int n = cb0 + nt2 * 16 + lk * 8;
                uint32_t addr = bbase + (uint32_t)(krow * B_PITCH + n * 2);
                LDSM4T(bf[nt2][0], bf[nt2][1], bf[nt2][2], bf[nt2][3], addr);
            }
#pragma unroll
            for (int mt = 0; mt < 4; mt++)
#pragma unroll
                for (int nt = 0; nt < 8; nt++)
                    mma_fp16(acc[mt][nt], af[mt], &bf[nt >> 1][(nt & 1) * 2]);
        }
        __syncthreads();
    }

    // epilogue: zero diagonal, duplicate K_T=2
    int e = eb >> 3, b_ = eb & 7;
    size_t obase = (size_t)(2 * e + 1) * (16ull << 20) + ((size_t)b_ << 10) * 2048;
#pragma unroll
    for (int mt = 0; mt < 4; mt++) {
#pragma unroll
        for (int half = 0; half < 2; half++) {
            int i = tm + rb0 + mt * 16 + gid + half * 8;
            size_t rowb = obase + (size_t)i * 2048;
#pragma unroll
            for (int nt = 0; nt < 8; nt++) {
                int j = tn + cb0 + nt * 8 + tig * 2;
                float2 v;
                v.x = acc[mt][nt][half * 2 + 0];
                v.y = acc[mt][nt][half * 2 + 1];
                if (i == j) v.x = 0.f;
                if (i == j + 1) v.y = 0.f;
                *(float2*)&out[rowb + j] = v;
                *(float2*)&out[rowb + 1024 + j] = v;
            }
        }
    }
}

// ---------------------------------------------------------------------------
extern "C" void kernel_launch(void* const* d_in, const int* in_sizes, int n_in,
                              void* d_out, int out_size) {
    const float* hd   = (const float*)d_in[0];
    const float* embd = (const float*)d_in[1];
    const float* embu = (const float*)d_in[2];
    const float* adj0 = (const float*)d_in[3];
    const float* adj1 = (const float*)d_in[4];
    const float* W1   = (const float*)d_in[5];
    const float* b1   = (const float*)d_in[6];
    const float* gam  = (const float*)d_in[7];
    const float* bet  = (const float*)d_in[8];
    const float* W2   = (const float*)d_in[9];
    const float* b2   = (const float*)d_in[10];
    const float* WQ   = (const float*)d_in[11];
    const float* WK   = (const float*)d_in[12];
    float* out = (float*)d_out;

    float *ph, *psc, *psh, *pdy, *pQ, *pK;
    __half* pgh;
    cudaGetSymbolAddress((void**)&ph,  d_h);
    cudaGetSymbolAddress((void**)&psc, d_scale);
    cudaGetSymbolAddress((void**)&psh, d_shift);
    cudaGetSymbolAddress((void**)&pdy, d_dy);
    cudaGetSymbolAddress((void**)&pQ,  d_Q);
    cudaGetSymbolAddress((void**)&pK,  d_K);
    cudaGetSymbolAddress((void**)&pgh, d_gh);

    k_h<<<2048, 256>>>(hd, W1, b1, ph);
    k_stats<<<64, 256>>>(ph, gam, bet, psc, psh);
    k_dy<<<1024, 256>>>(ph, psc, psh, W2, b2, pdy);
    k_qk<<<1024, 128>>>(pdy, embd, embu, WQ, WK, pQ, pK);

    int attn_smem = (256 + 32 * KT_P + 8 * 1024) * (int)sizeof(float);
    cudaFuncSetAttribute(k_attn, cudaFuncAttributeMaxDynamicSharedMemorySize, attn_smem);
    k_attn<<<2048, 256, attn_smem>>>(pQ, pK, adj0, adj1, pgh, out);

    cudaFuncSetAttribute(k_gemm_fp16, cudaFuncAttributeMaxDynamicSharedMemorySize, GEMM_SMEM);
    dim3 ggrid(4, 8, 16);
    k_gemm_fp16<<<ggrid, 256, GEMM_SMEM>>>(pgh, out);
}

// round 7
// speedup vs baseline: 4.2709x; 1.1455x over previous
#include <cuda_runtime.h>
#include <cuda_fp16.h>
#include <cstdint>
#include <math.h>

// Problem constants
#define NB 8
#define LL 12
#define NN 1024
#define HH 32
#define H2 64
#define AF 48
#define NDIM 16

// Scratch (device globals)
__device__ float d_h[8192 * H2];
__device__ float d_scale[H2];
__device__ float d_shift[H2];
__device__ float d_Q[2 * 8192 * HH];
__device__ float d_K[2 * 8192 * HH];
__device__ __half d_gh[16ull * 1024 * 1024];   // 32 MB fp16 graphs

extern __shared__ char dynsmem[];

// ---------------------------------------------------------------------------
#define SWZ128(o) ((o) ^ (((o) >> 3) & 0x70))
#define CP_ASYNC16(dst, src) asm volatile("cp.async.cg.shared.global [%0], [%1], 16;" :: "r"(dst), "l"(src))
#define CP_COMMIT() asm volatile("cp.async.commit_group;" ::: "memory")
#define CP_WAIT1() asm volatile("cp.async.wait_group 1;" ::: "memory")
#define CP_WAIT0() asm volatile("cp.async.wait_group 0;" ::: "memory")
#define LDSM4(r0, r1, r2, r3, addr) \
    asm volatile("ldmatrix.sync.aligned.m8n8.x4.shared.b16 {%0,%1,%2,%3}, [%4];" \
        : "=r"(r0), "=r"(r1), "=r"(r2), "=r"(r3) : "r"(addr))
#define LDSM4T(r0, r1, r2, r3, addr) \
    asm volatile("ldmatrix.sync.aligned.m8n8.x4.trans.shared.b16 {%0,%1,%2,%3}, [%4];" \
        : "=r"(r0), "=r"(r1), "=r"(r2), "=r"(r3) : "r"(addr))

__device__ __forceinline__ uint32_t smem_u32(const void* p) {
    uint32_t a;
    asm("{ .reg .u64 t; cvta.to.shared.u64 t, %1; cvt.u32.u64 %0, t; }" : "=r"(a) : "l"(p));
    return a;
}
__device__ __forceinline__ float ex2(float x) {
    float y;
    asm("ex2.approx.ftz.f32 %0, %1;" : "=f"(y) : "f"(x));
    return y;
}
__device__ __forceinline__ void mma_fp16(float* c, const uint32_t* a, const uint32_t* b) {
    asm volatile(
        "mma.sync.aligned.m16n8k16.row.col.f32.f16.f16.f32 "
        "{%0,%1,%2,%3}, {%4,%5,%6,%7}, {%8,%9}, {%0,%1,%2,%3};"
        : "+f"(c[0]), "+f"(c[1]), "+f"(c[2]), "+f"(c[3])
        : "r"(a[0]), "r"(a[1]), "r"(a[2]), "r"(a[3]), "r"(b[0]), "r"(b[1]));
}

// ---------------------------------------------------------------------------
// Kernel 1: h = relu(X @ W1 + b1)
__global__ void k_h(const float* __restrict__ hd, const float* __restrict__ W1,
                    const float* __restrict__ b1, float* __restrict__ h) {
    __shared__ float sW[LL * H2];
    __shared__ float sb[H2];
    int tid = threadIdx.x;
    for (int i = tid; i < LL * H2; i += 256) sW[i] = W1[i];
    if (tid < H2) sb[tid] = b1[tid];
    __syncthreads();
    int row = blockIdx.x * 4 + (tid >> 6);
    int col = tid & 63;
    int b = row >> 10, n = row & 1023;
    float acc = sb[col];
#pragma unroll
    for (int l = 0; l < LL; l++)
        acc += hd[((size_t)(b * LL + l) << 10) + n] * sW[l * H2 + col];
    h[(size_t)row * H2 + col] = fmaxf(acc, 0.f);
}

// ---------------------------------------------------------------------------
// Kernel 2: BN stats -> folded scale/shift
__global__ void k_stats(const float* __restrict__ h, const float* __restrict__ gamma,
                        const float* __restrict__ beta,
                        float* __restrict__ scale, float* __restrict__ shift) {
    int c = blockIdx.x;
    float s = 0.f, s2 = 0.f;
    for (int r = threadIdx.x; r < 8192; r += 256) {
        float v = h[(size_t)r * H2 + c];
        s += v; s2 += v * v;
    }
    __shared__ float rs[256], rs2[256];
    rs[threadIdx.x] = s; rs2[threadIdx.x] = s2;
    __syncthreads();
    for (int o = 128; o > 0; o >>= 1) {
        if (threadIdx.x < o) { rs[threadIdx.x] += rs[threadIdx.x + o]; rs2[threadIdx.x] += rs2[threadIdx.x + o]; }
        __syncthreads();
    }
    if (threadIdx.x == 0) {
        float mu = rs[0] * (1.f / 8192.f);
        float var = rs2[0] * (1.f / 8192.f) - mu * mu;
        float sc = gamma[c] * rsqrtf(var + 1e-5f);
        scale[c] = sc;
        shift[c] = beta[c] - mu * sc;
    }
}

// ---------------------------------------------------------------------------
// Kernel 3: fused dy + Q/K projections. 16 rows per 128-thread block, 512 blocks.
// dy = BN(h)@W2+b2; Q/K for both embeddings reuse the shared dy-part dot.
__global__ void k_dyqk(const float* __restrict__ h, const float* __restrict__ scale,
                       const float* __restrict__ shift, const float* __restrict__ W2,
                       const float* __restrict__ b2,
                       const float* __restrict__ embd, const float* __restrict__ embu,
                       const float* __restrict__ WQ, const float* __restrict__ WK,
                       float* __restrict__ Q, float* __restrict__ K) {
    __shared__ float sW2[H2 * HH];       // 2048
    __shared__ float sWQ[AF * HH];       // 1536
    __shared__ float sWK[AF * HH];
    __shared__ float sb2[HH];
    __shared__ float ssc[H2], ssh[H2];
    __shared__ float shh[16][H2];
    __shared__ float sed[16][NDIM], seu[16][NDIM];
    __shared__ float sdy[16][HH];
    int tid = threadIdx.x;
    int row0 = blockIdx.x * 16;
    int n0 = row0 & 1023;

    for (int i = tid; i < H2 * HH; i += 128) sW2[i] = W2[i];
    for (int i = tid; i < AF * HH; i += 128) { sWQ[i] = WQ[i]; sWK[i] = WK[i]; }
    if (tid < HH) sb2[tid] = b2[tid];
    if (tid < H2) { ssc[tid] = scale[tid]; ssh[tid] = shift[tid]; }
    for (int i = tid; i < 16 * NDIM; i += 128) {
        int r = i >> 4, k = i & 15;
        sed[r][k] = embd[(n0 + r) * NDIM + k];
        seu[r][k] = embu[(n0 + r) * NDIM + k];
    }
    __syncthreads();
    for (int i = tid; i < 16 * H2; i += 128) {
        int r = i >> 6, c = i & 63;
        shh[r][c] = h[(size_t)(row0 + r) * H2 + c] * ssc[c] + ssh[c];
    }
    __syncthreads();

    int rr = tid >> 5, c = tid & 31;
#pragma unroll
    for (int p = 0; p < 4; p++) {
        int r = p * 4 + rr;
        float acc = sb2[c];
#pragma unroll
        for (int k = 0; k < H2; k++) acc += shh[r][k] * sW2[k * HH + c];
        sdy[r][c] = acc;
    }
    __syncthreads();

#pragma unroll
    for (int p = 0; p < 4; p++) {
        int r = p * 4 + rr;
        float q0 = 0.f, k0 = 0.f;
#pragma unroll
        for (int k = 0; k < HH; k++) {
            float f = sdy[r][k];
            q0 += f * sWQ[k * HH + c];
            k0 += f * sWK[k * HH + c];
        }
        float qd = q0, qu = q0, kd = k0, ku = k0;
#pragma unroll
        for (int k = 0; k < NDIM; k++) {
            float wq = sWQ[(HH + k) * HH + c];
            float wk = sWK[(HH + k) * HH + c];
            qd += sed[r][k] * wq; qu += seu[r][k] * wq;
            kd += sed[r][k] * wk; ku += seu[r][k] * wk;
        }
        size_t od = (size_t)(row0 + r) * HH + c;
        size_t ou = (size_t)(8192 + row0 + r) * HH + c;
        Q[od] = qd; Q[ou] = qu;
        K[od] = kd; K[ou] = ku;
    }
}

// ---------------------------------------------------------------------------
// Kernel 4: attention -> normalized masked g (fp16); order-1 outputs (s=2e)
// Phase-1 logits pre-scaled by lscale*log2(e); exp via raw EX2 (max cancels).
#define KT_P 265
#define PSC 0.25507600725815733f   // (1/sqrt(32)) * log2(e)
__global__ void k_attn(const float* __restrict__ Q, const float* __restrict__ K,
                       const float* __restrict__ adj0, const float* __restrict__ adj1,
                       __half* __restrict__ gh, float* __restrict__ out) {
    float* smemf = (float*)dynsmem;
    float* sQ = smemf;                     // 256
    float* sKT = smemf + 256;              // 32 * 265
    float* sE = smemf + 256 + 8480;        // 8192
    int tid = threadIdx.x;
    int blk = blockIdx.x;
    int e = blk >> 10;
    int rb = blk & 1023;
    int b = rb >> 7;
    int row0 = (rb & 127) * 8;
    const float* adj = e ? adj1 : adj0;
    size_t qbase = ((size_t)e * 8192 + b * 1024 + row0) * HH;
    size_t kbase = ((size_t)e * 8192 + b * 1024) * HH;
    sQ[tid] = Q[qbase + tid];

    for (int t = 0; t < 4; t++) {
        __syncthreads();
        for (int i = tid; i < 8192; i += 256) {
            int r = i >> 5, c = i & 31;
            sKT[c * KT_P + r] = K[kbase + (size_t)t * 8192 + i];
        }
        __syncthreads();
        float kreg[32];
#pragma unroll
        for (int k = 0; k < 32; k++) kreg[k] = sKT[k * KT_P + tid];
#pragma unroll
        for (int r = 0; r < 8; r++) {
            float acc = 0.f;
#pragma unroll
            for (int q4 = 0; q4 < 8; q4++) {
                float4 qv = *(const float4*)&sQ[r * 32 + q4 * 4];
                acc += qv.x * kreg[q4 * 4 + 0];
                acc += qv.y * kreg[q4 * 4 + 1];
                acc += qv.z * kreg[q4 * 4 + 2];
                acc += qv.w * kreg[q4 * 4 + 3];
            }
            sE[r * 1024 + t * 256 + tid] = acc * PSC;
        }
    }
    __syncthreads();

    int w = tid >> 5, lane = tid & 31;
    int n = row0 + w;
    float v[32];
    float sum = 0.f;
#pragma unroll
    for (int i = 0; i < 32; i++) {
        int m = i * 32 + lane;
        float e2 = ex2(sE[w * 1024 + m]);
        float a = adj[(size_t)n * 1024 + m];
        float vv = e2 * a + e2 * 1e-7f;
        v[i] = vv;
        sum += vv;
    }
    for (int o = 16; o > 0; o >>= 1) sum += __shfl_xor_sync(0xffffffffu, sum, o);
    float inv = 1.f / sum;
    if (!isfinite(inv)) inv = 0.f;

    size_t gbase = ((size_t)e * 8192 + b * 1024 + n) * 1024;
    size_t obase = (size_t)(2 * e) * (16ull << 20) + ((size_t)b * 1024 + n) * 2048;
#pragma unroll
    for (int i = 0; i < 32; i++) {
        int m = i * 32 + lane;
        float val = v[i] * inv;
        gh[gbase + m] = __float2half_rn(val);
        float vo = (m == n) ? 0.f : val;
        out[obase + m] = vo;
        out[obase + 1024 + m] = vo;
    }
}

// ---------------------------------------------------------------------------
// Kernel 5: fp16 mma.sync GEMM. Block tile 128x128, 128 threads (4 warps,
// each 64x64), k-chunk 64, cp.async double buffering, 2 CTAs/SM.
#define A_BYTES 16384              // 128 rows x 128B
#define B_PITCH 272                // 256B data + 16B pad per k-row
#define B_BYTES (64 * B_PITCH)     // 17408
#define GEMM_SMEM (2 * A_BYTES + 2 * B_BYTES)   // 67584

__global__ void __launch_bounds__(128, 2)
k_gemm_fp16(const __half* __restrict__ gh, float* __restrict__ out) {
    char* smem = dynsmem;
    uint32_t sb = smem_u32(smem);
    const uint32_t AOFF[2] = {0u, A_BYTES};
    const uint32_t BOFF[2] = {2 * A_BYTES, 2 * A_BYTES + B_BYTES};
    int tid = threadIdx.x;
    int eb = blockIdx.z;
    int tm = blockIdx.y * 128, tn = blockIdx.x * 128;
    size_t base = (size_t)eb << 20;

    int wid = tid >> 5, lane = tid & 31;
    int gid = lane >> 2, tig = lane & 3;
    int warp_m = wid & 1, warp_n = wid >> 1;
    int rb0 = warp_m * 64, cb0 = warp_n * 64;

    float acc[4][8][4];
#pragma unroll
    for (int i = 0; i < 4; i++)
#pragma unroll
        for (int j = 0; j < 8; j++)
#pragma unroll
            for (int q = 0; q < 4; q++) acc[i][j][q] = 0.f;

    int lr = lane & 7;
    int lm = (lane >> 3) & 1;
    int lk = lane >> 4;

    auto load_chunk = [&](int c, int buf) {
        int k0 = c * 64;
#pragma unroll
        for (int q = 0; q < 8; q++) {
            int idx = tid + q * 128;
            int r = idx >> 3, s = idx & 7;
            uint32_t dst = sb + AOFF[buf] + SWZ128((uint32_t)(r * 128 + s * 16));
            const __half* src = gh + base + ((size_t)(tm + r) << 10) + k0 + s * 8;
            CP_ASYNC16(dst, src);
        }
#pragma unroll
        for (int q = 0; q < 8; q++) {
            int idx = tid + q * 128;
            int r = idx >> 4, s = idx & 15;
            uint32_t dst = sb + BOFF[buf] + (uint32_t)(r * B_PITCH + s * 16);
            const __half* src = gh + base + ((size_t)(k0 + r) << 10) + tn + s * 8;
            CP_ASYNC16(dst, src);
        }
        CP_COMMIT();
    };

    load_chunk(0, 0);
    for (int c = 0; c < 16; c++) {
        int buf = c & 1;
        if (c < 15) { load_chunk(c + 1, buf ^ 1); CP_WAIT1(); }
        else        { CP_WAIT0(); }
        __syncthreads();
        uint32_t abase = sb + AOFF[buf];
        uint32_t bbase = sb + BOFF[buf];
#pragma unroll
        for (int kk = 0; kk < 64; kk += 16) {
            uint32_t af[4][4], bf[4][4];
#pragma unroll
            for (int mt = 0; mt < 4; mt++) {
                int m = rb0 + mt * 16 + lm * 8 + lr;
                uint32_t addr = abase + SWZ128((uint32_t)(m * 128 + kk * 2 + lk * 16));
                LDSM4(af[mt][0], af[mt][1], af[mt][2], af[mt][3], addr);
            }
#pragma unroll
            for (int nt2 = 0; nt2 < 4; nt2++) {
                int krow = kk + lm * 8 + lr;
                int n = cb0 + nt2 * 16 + lk * 8;
                uint32_t addr = bbase + (uint32_t)(krow * B_PITCH + n * 2);
                LDSM4T(bf[nt2][0], bf[nt2][1], bf[nt2][2], bf[nt2][3], addr);
            }
#pragma unroll
            for (int mt = 0; mt < 4; mt++)
#pragma unroll
                for (int nt = 0; nt < 8; nt++)
                    mma_fp16(acc[mt][nt], af[mt], &bf[nt >> 1][(nt & 1) * 2]);
        }
        __syncthreads();
    }

    // epilogue: zero diagonal, duplicate K_T=2
    int e = eb >> 3, b_ = eb & 7;
    size_t obase = (size_t)(2 * e + 1) * (16ull << 20) + ((size_t)b_ << 10) * 2048;
#pragma unroll
    for (int mt = 0; mt < 4; mt++) {
#pragma unroll
        for (int half = 0; half < 2; half++) {
            int i = tm + rb0 + mt * 16 + gid + half * 8;
            size_t rowb = obase + (size_t)i * 2048;
#pragma unroll
            for (int nt = 0; nt < 8; nt++) {
                int j = tn + cb0 + nt * 8 + tig * 2;
                float2 v;
                v.x = acc[mt][nt][half * 2 + 0];
                v.y = acc[mt][nt][half * 2 + 1];
                if (i == j) v.x = 0.f;
                if (i == j + 1) v.y = 0.f;
                *(float2*)&out[rowb + j] = v;
                *(float2*)&out[rowb + 1024 + j] = v;
            }
        }
    }
}

// ---------------------------------------------------------------------------
extern "C" void kernel_launch(void* const* d_in, const int* in_sizes, int n_in,
                              void* d_out, int out_size) {
    const float* hd   = (const float*)d_in[0];
    const float* embd = (const float*)d_in[1];
    const float* embu = (const float*)d_in[2];
    const float* adj0 = (const float*)d_in[3];
    const float* adj1 = (const float*)d_in[4];
    const float* W1   = (const float*)d_in[5];
    const float* b1   = (const float*)d_in[6];
    const float* gam  = (const float*)d_in[7];
    const float* bet  = (const float*)d_in[8];
    const float* W2   = (const float*)d_in[9];
    const float* b2   = (const float*)d_in[10];
    const float* WQ   = (const float*)d_in[11];
    const float* WK   = (const float*)d_in[12];
    float* out = (float*)d_out;

    float *ph, *psc, *psh, *pQ, *pK;
    __half* pgh;
    cudaGetSymbolAddress((void**)&ph,  d_h);
    cudaGetSymbolAddress((void**)&psc, d_scale);
    cudaGetSymbolAddress((void**)&psh, d_shift);
    cudaGetSymbolAddress((void**)&pQ,  d_Q);
    cudaGetSymbolAddress((void**)&pK,  d_K);
    cudaGetSymbolAddress((void**)&pgh, d_gh);

    k_h<<<2048, 256>>>(hd, W1, b1, ph);
    k_stats<<<64, 256>>>(ph, gam, bet, psc, psh);
    k_dyqk<<<512, 128>>>(ph, psc, psh, W2, b2, embd, embu, WQ, WK, pQ, pK);

    int attn_smem = (256 + 32 * KT_P + 8 * 1024) * (int)sizeof(float);
    cudaFuncSetAttribute(k_attn, cudaFuncAttributeMaxDynamicSharedMemorySize, attn_smem);
    k_attn<<<2048, 256, attn_smem>>>(pQ, pK, adj0, adj1, pgh, out);

    cudaFuncSetAttribute(k_gemm_fp16, cudaFuncAttributeMaxDynamicSharedMemorySize, GEMM_SMEM);
    dim3 ggrid(8, 8, 16);
    k_gemm_fp16<<<ggrid, 128, GEMM_SMEM>>>(pgh, out);
}